// round 1
// baseline (speedup 1.0000x reference)
#include <cuda_runtime.h>
#include <math.h>

#define NN 20000
#define MM 32
#define INDIM 256
#define OUTDIM 256
#define NHEAD 4
#define HDIM 64
#define LN_EPS 1e-5f
#define NEG_INF -1.0e9f

// scratch buffers
__device__ float g_hproj[NN * OUTDIM];   // ~20.5 MB, fits in L2
__device__ float g_el[NN * NHEAD];
__device__ float g_er[NN * NHEAD];

// ----------------------------------------------------------------------------
// Kernel 1: h_proj = h @ W   (fp32 SIMT GEMM, BM=64 x BN=256 tile, BK=16)
// 256 threads, 8x8 microtile per thread.
// ----------------------------------------------------------------------------
#define BM 64
#define BK 16

__global__ __launch_bounds__(256, 2)
void gemm_kernel(const float* __restrict__ h, const float* __restrict__ W) {
    __shared__ float As[BK][68];      // [k][row], padded for bank-conflict-free stores
    __shared__ float Bs[BK][256];     // [k][col]

    const int block_row = blockIdx.x * BM;
    const int tid = threadIdx.x;
    const int ry = tid >> 5;          // 0..7 : row-group (= warp id)
    const int cx = tid & 31;          // 0..31: col-group

    float acc[8][8];
#pragma unroll
    for (int i = 0; i < 8; i++)
#pragma unroll
        for (int j = 0; j < 8; j++) acc[i][j] = 0.0f;

    // A-load mapping: each thread loads one float4 of the 64x16 tile
    const int a_row = tid >> 2;            // 0..63
    const int a_k4  = (tid & 3) * 4;       // 0,4,8,12
    const int a_grow = block_row + a_row;
    const bool a_valid = (a_grow < NN);

    for (int k0 = 0; k0 < INDIM; k0 += BK) {
        // load A tile (transposed into As[k][row])
        float4 av = make_float4(0.f, 0.f, 0.f, 0.f);
        if (a_valid)
            av = *reinterpret_cast<const float4*>(&h[a_grow * INDIM + k0 + a_k4]);
        As[a_k4 + 0][a_row] = av.x;
        As[a_k4 + 1][a_row] = av.y;
        As[a_k4 + 2][a_row] = av.z;
        As[a_k4 + 3][a_row] = av.w;

        // load B tile: 16x256 floats = 1024 float4, 4 per thread, coalesced
#pragma unroll
        for (int jj = 0; jj < 4; jj++) {
            int id = tid + 256 * jj;       // float4 index
            int kk = id >> 6;              // 0..15
            int cf = (id & 63) * 4;        // col
            float4 bv = *reinterpret_cast<const float4*>(&W[(k0 + kk) * OUTDIM + cf]);
            *reinterpret_cast<float4*>(&Bs[kk][cf]) = bv;
        }
        __syncthreads();

#pragma unroll
        for (int kk = 0; kk < BK; kk++) {
            float a[8], b[8];
            float4 a0 = *reinterpret_cast<const float4*>(&As[kk][ry * 8]);
            float4 a1 = *reinterpret_cast<const float4*>(&As[kk][ry * 8 + 4]);
            a[0]=a0.x; a[1]=a0.y; a[2]=a0.z; a[3]=a0.w;
            a[4]=a1.x; a[5]=a1.y; a[6]=a1.z; a[7]=a1.w;
            float4 b0 = *reinterpret_cast<const float4*>(&Bs[kk][cx * 8]);
            float4 b1 = *reinterpret_cast<const float4*>(&Bs[kk][cx * 8 + 4]);
            b[0]=b0.x; b[1]=b0.y; b[2]=b0.z; b[3]=b0.w;
            b[4]=b1.x; b[5]=b1.y; b[6]=b1.z; b[7]=b1.w;
#pragma unroll
            for (int i = 0; i < 8; i++)
#pragma unroll
                for (int j = 0; j < 8; j++)
                    acc[i][j] = fmaf(a[i], b[j], acc[i][j]);
        }
        __syncthreads();
    }

    // store: rows ry*8..ry*8+7, cols cx*8..cx*8+7 (float4 x2 per row)
#pragma unroll
    for (int i = 0; i < 8; i++) {
        int grow = block_row + ry * 8 + i;
        if (grow < NN) {
            float4 v0 = make_float4(acc[i][0], acc[i][1], acc[i][2], acc[i][3]);
            float4 v1 = make_float4(acc[i][4], acc[i][5], acc[i][6], acc[i][7]);
            *reinterpret_cast<float4*>(&g_hproj[grow * OUTDIM + cx * 8])     = v0;
            *reinterpret_cast<float4*>(&g_hproj[grow * OUTDIM + cx * 8 + 4]) = v1;
        }
    }
}

// ----------------------------------------------------------------------------
// Kernel 2: el[n][h] = sum_d hproj[n][h*64+d]*a_l[h][d]; same for er.
// One block (256 threads) per node.
// ----------------------------------------------------------------------------
__global__ __launch_bounds__(256)
void eler_kernel(const float* __restrict__ a_l, const float* __restrict__ a_r) {
    const int n = blockIdx.x;
    const int c = threadIdx.x;
    float hp = g_hproj[n * OUTDIM + c];
    float pl = hp * a_l[c];   // a_l flattened [H*D] == channel index
    float pr = hp * a_r[c];
#pragma unroll
    for (int off = 16; off > 0; off >>= 1) {
        pl += __shfl_xor_sync(0xffffffffu, pl, off);
        pr += __shfl_xor_sync(0xffffffffu, pr, off);
    }
    __shared__ float sl[8], sr[8];
    if ((c & 31) == 0) { sl[c >> 5] = pl; sr[c >> 5] = pr; }
    __syncthreads();
    if (c < NHEAD) {
        g_el[n * NHEAD + c] = sl[2 * c] + sl[2 * c + 1];
        g_er[n * NHEAD + c] = sr[2 * c] + sr[2 * c + 1];
    }
}

// ----------------------------------------------------------------------------
// Kernel 3: attention + residual + GELU + LayerNorm. One block per node.
// ----------------------------------------------------------------------------
__device__ __forceinline__ float block_reduce_sum(float v, float* sred, int tid) {
#pragma unroll
    for (int off = 16; off > 0; off >>= 1)
        v += __shfl_xor_sync(0xffffffffu, v, off);
    if ((tid & 31) == 0) sred[tid >> 5] = v;
    __syncthreads();
    float t = 0.0f;
    if (tid < 8) {
        t = sred[tid];
#pragma unroll
        for (int off = 4; off > 0; off >>= 1)
            t += __shfl_xor_sync(0xffu, t, off);
        if (tid == 0) sred[0] = t;
    }
    __syncthreads();
    t = sred[0];
    __syncthreads();
    return t;
}

__global__ __launch_bounds__(256)
void attn_kernel(const int* __restrict__ nidx, const int* __restrict__ nmask,
                 const float* __restrict__ gamma, const float* __restrict__ beta,
                 float* __restrict__ out) {
    const int n = blockIdx.x;
    const int tid = threadIdx.x;
    const int w = tid >> 5;
    const int lane = tid & 31;

    __shared__ float s_alpha[NHEAD][MM];
    __shared__ int   s_nbr[MM];
    __shared__ float s_red[8];

    if (w < NHEAD) {
        int nb = nidx[n * MM + lane];
        int mk = nmask[n * MM + lane];
        if (w == 0) s_nbr[lane] = nb;
        float e = g_el[n * NHEAD + w] + g_er[nb * NHEAD + w];
        e = (e >= 0.0f) ? e : 0.2f * e;                 // leaky relu, slope 0.2
        if (mk == 0) e = NEG_INF;
        float mx = e;
#pragma unroll
        for (int off = 16; off > 0; off >>= 1)
            mx = fmaxf(mx, __shfl_xor_sync(0xffffffffu, mx, off));
        float ex = expf(e - mx);                        // all-masked -> exp(0)=1 each
        float sm = ex;
#pragma unroll
        for (int off = 16; off > 0; off >>= 1)
            sm += __shfl_xor_sync(0xffffffffu, sm, off);
        s_alpha[w][lane] = ex / sm;
    }
    __syncthreads();

    const int hh = tid >> 6;   // head of this channel
    float acc = 0.0f;
#pragma unroll
    for (int m = 0; m < MM; m++) {
        acc = fmaf(s_alpha[hh][m], g_hproj[s_nbr[m] * OUTDIM + tid], acc);
    }

    float x = acc + g_hproj[n * OUTDIM + tid];          // residual
    // exact GELU: 0.5*x*(1+erf(x/sqrt(2)))
    float g = 0.5f * x * (1.0f + erff(x * 0.70710678118654752f));

    // LayerNorm (two-pass)
    float mean = block_reduce_sum(g, s_red, tid) * (1.0f / 256.0f);
    float d = g - mean;
    float var = block_reduce_sum(d * d, s_red, tid) * (1.0f / 256.0f);
    out[n * OUTDIM + tid] = d * rsqrtf(var + LN_EPS) * gamma[tid] + beta[tid];
}

// ----------------------------------------------------------------------------
extern "C" void kernel_launch(void* const* d_in, const int* in_sizes, int n_in,
                              void* d_out, int out_size) {
    const float* h     = (const float*)d_in[0];
    const int*   nidx  = (const int*)  d_in[1];
    const int*   nmask = (const int*)  d_in[2];
    const float* W     = (const float*)d_in[3];
    const float* a_l   = (const float*)d_in[4];
    const float* a_r   = (const float*)d_in[5];
    const float* gamma = (const float*)d_in[6];
    const float* beta  = (const float*)d_in[7];
    float* out = (float*)d_out;

    gemm_kernel<<<(NN + BM - 1) / BM, 256>>>(h, W);
    eler_kernel<<<NN, 256>>>(a_l, a_r);
    attn_kernel<<<NN, 256>>>(nidx, nmask, gamma, beta, out);
}

// round 2
// speedup vs baseline: 1.3985x; 1.3985x over previous
#include <cuda_runtime.h>
#include <math.h>
#include <stdint.h>

#define NN 20000
#define MM 32
#define INDIM 256
#define OUTDIM 256
#define NHEAD 4
#define HDIM 64
#define LN_EPS 1e-5f
#define NEG_INF -1.0e9f

// scratch buffers
__device__ float g_hproj[NN * OUTDIM];   // ~20.5 MB, fits in L2
__device__ float g_el[NN * NHEAD];
__device__ float g_er[NN * NHEAD];

// ----------------------------------------------------------------------------
// Kernel 1: h_proj = h @ W  via TF32 mma.sync (m16n8k8).
// Block tile 128x128, BK=32, 256 threads (8 warps: 4 along M x 2 along N).
// Warp tile 32x64 = 2 m-tiles x 8 n-tiles of 16x8.
// A smem: [128][36] tf32 bits (pad 36 -> conflict-free frag loads).
// B smem: [32][136] tf32 bits (pad 136 -> conflict-free frag loads).
// ----------------------------------------------------------------------------
#define AS_STRIDE 36
#define BS_STRIDE 136

__device__ __forceinline__ uint32_t f32_to_tf32(float x) {
    uint32_t u;
    asm("cvt.rna.tf32.f32 %0, %1;" : "=r"(u) : "f"(x));
    return u;
}

__device__ __forceinline__ void mma_tf32(float* d, const uint32_t* a, const uint32_t* b) {
    asm volatile(
        "mma.sync.aligned.m16n8k8.row.col.f32.tf32.tf32.f32 "
        "{%0,%1,%2,%3}, {%4,%5,%6,%7}, {%8,%9}, {%0,%1,%2,%3};"
        : "+f"(d[0]), "+f"(d[1]), "+f"(d[2]), "+f"(d[3])
        : "r"(a[0]), "r"(a[1]), "r"(a[2]), "r"(a[3]), "r"(b[0]), "r"(b[1]));
}

__global__ __launch_bounds__(256, 2)
void gemm_tf32_kernel(const float* __restrict__ h, const float* __restrict__ W) {
    __shared__ uint32_t As[128 * AS_STRIDE];
    __shared__ uint32_t Bs[32 * BS_STRIDE];

    const int tid = threadIdx.x;
    const int lane = tid & 31;
    const int w = tid >> 5;
    const int wm = w & 3;            // 0..3 warp row
    const int wn = w >> 2;           // 0..1 warp col
    const int m0w = wm * 32;
    const int n0w = wn * 64;

    const int rowBase = blockIdx.x * 128;
    const int nBase = blockIdx.y * 128;

    float acc[2][8][4];
#pragma unroll
    for (int i = 0; i < 2; i++)
#pragma unroll
        for (int j = 0; j < 8; j++)
#pragma unroll
            for (int k = 0; k < 4; k++) acc[i][j][k] = 0.0f;

    const int lr = lane >> 2;   // 0..7
    const int lc = lane & 3;    // 0..3

    for (int kt = 0; kt < INDIM; kt += 32) {
        // ---- fill A tile [128 x 32] ----
#pragma unroll
        for (int q = 0; q < 4; q++) {
            int id = tid + 256 * q;
            int r = id >> 3;
            int j = id & 7;
            int gr = rowBase + r;
            float4 v = make_float4(0.f, 0.f, 0.f, 0.f);
            if (gr < NN)
                v = *reinterpret_cast<const float4*>(&h[gr * INDIM + kt + 4 * j]);
            uint4 t;
            t.x = f32_to_tf32(v.x); t.y = f32_to_tf32(v.y);
            t.z = f32_to_tf32(v.z); t.w = f32_to_tf32(v.w);
            *reinterpret_cast<uint4*>(&As[r * AS_STRIDE + 4 * j]) = t;
        }
        // ---- fill B tile [32 x 128] ----
#pragma unroll
        for (int q = 0; q < 4; q++) {
            int id = tid + 256 * q;
            int k = id >> 5;
            int c0 = (id & 31) * 4;
            float4 v = *reinterpret_cast<const float4*>(&W[(kt + k) * OUTDIM + nBase + c0]);
            uint4 t;
            t.x = f32_to_tf32(v.x); t.y = f32_to_tf32(v.y);
            t.z = f32_to_tf32(v.z); t.w = f32_to_tf32(v.w);
            *reinterpret_cast<uint4*>(&Bs[k * BS_STRIDE + c0]) = t;
        }
        __syncthreads();

        // ---- compute: 4 k-steps of 8 ----
#pragma unroll
        for (int g = 0; g < 4; g++) {
            const int kc = g * 8 + lc;
            uint32_t a[2][4];
#pragma unroll
            for (int tm = 0; tm < 2; tm++) {
                int r = m0w + tm * 16 + lr;
                a[tm][0] = As[r * AS_STRIDE + kc];
                a[tm][1] = As[(r + 8) * AS_STRIDE + kc];
                a[tm][2] = As[r * AS_STRIDE + kc + 4];
                a[tm][3] = As[(r + 8) * AS_STRIDE + kc + 4];
            }
            uint32_t b[8][2];
#pragma unroll
            for (int tn = 0; tn < 8; tn++) {
                int col = n0w + tn * 8 + lr;
                b[tn][0] = Bs[kc * BS_STRIDE + col];
                b[tn][1] = Bs[(kc + 4) * BS_STRIDE + col];
            }
#pragma unroll
            for (int tm = 0; tm < 2; tm++)
#pragma unroll
                for (int tn = 0; tn < 8; tn++)
                    mma_tf32(acc[tm][tn], a[tm], b[tn]);
        }
        __syncthreads();
    }

    // ---- epilogue: store to g_hproj ----
#pragma unroll
    for (int tm = 0; tm < 2; tm++) {
#pragma unroll
        for (int tn = 0; tn < 8; tn++) {
            int gr0 = rowBase + m0w + tm * 16 + lr;
            int gc = nBase + n0w + tn * 8 + 2 * lc;
            if (gr0 < NN)
                *reinterpret_cast<float2*>(&g_hproj[gr0 * OUTDIM + gc]) =
                    make_float2(acc[tm][tn][0], acc[tm][tn][1]);
            if (gr0 + 8 < NN)
                *reinterpret_cast<float2*>(&g_hproj[(gr0 + 8) * OUTDIM + gc]) =
                    make_float2(acc[tm][tn][2], acc[tm][tn][3]);
        }
    }
}

// ----------------------------------------------------------------------------
// Kernel 2: el[n][h], er[n][h] dot products. One block (256 threads) per node.
// ----------------------------------------------------------------------------
__global__ __launch_bounds__(256)
void eler_kernel(const float* __restrict__ a_l, const float* __restrict__ a_r) {
    const int n = blockIdx.x;
    const int c = threadIdx.x;
    float hp = g_hproj[n * OUTDIM + c];
    float pl = hp * a_l[c];
    float pr = hp * a_r[c];
#pragma unroll
    for (int off = 16; off > 0; off >>= 1) {
        pl += __shfl_xor_sync(0xffffffffu, pl, off);
        pr += __shfl_xor_sync(0xffffffffu, pr, off);
    }
    __shared__ float sl[8], sr[8];
    if ((c & 31) == 0) { sl[c >> 5] = pl; sr[c >> 5] = pr; }
    __syncthreads();
    if (c < NHEAD) {
        g_el[n * NHEAD + c] = sl[2 * c] + sl[2 * c + 1];
        g_er[n * NHEAD + c] = sr[2 * c] + sr[2 * c + 1];
    }
}

// ----------------------------------------------------------------------------
// Kernel 3: attention + residual + GELU + LayerNorm. One block per node.
// ----------------------------------------------------------------------------
__device__ __forceinline__ float block_reduce_sum(float v, float* sred, int tid) {
#pragma unroll
    for (int off = 16; off > 0; off >>= 1)
        v += __shfl_xor_sync(0xffffffffu, v, off);
    if ((tid & 31) == 0) sred[tid >> 5] = v;
    __syncthreads();
    float t = 0.0f;
    if (tid < 8) {
        t = sred[tid];
#pragma unroll
        for (int off = 4; off > 0; off >>= 1)
            t += __shfl_xor_sync(0xffu, t, off);
        if (tid == 0) sred[0] = t;
    }
    __syncthreads();
    t = sred[0];
    __syncthreads();
    return t;
}

__global__ __launch_bounds__(256)
void attn_kernel(const int* __restrict__ nidx, const int* __restrict__ nmask,
                 const float* __restrict__ gamma, const float* __restrict__ beta,
                 float* __restrict__ out) {
    const int n = blockIdx.x;
    const int tid = threadIdx.x;
    const int w = tid >> 5;
    const int lane = tid & 31;

    __shared__ float  s_alpha[NHEAD][MM];
    __shared__ int    s_nbr[MM];
    __shared__ int    s_mask[MM];
    __shared__ float4 s_er4[MM];
    __shared__ float  s_red[8];

    // warp 0: gather neighbor indices, masks, and er float4s (one coalesced-ish pass)
    if (tid < 32) {
        int nb = nidx[n * MM + tid];
        s_nbr[tid] = nb;
        s_mask[tid] = nmask[n * MM + tid];
        s_er4[tid] = *reinterpret_cast<const float4*>(&g_er[nb * NHEAD]);
    }
    __syncthreads();

    if (w < NHEAD) {
        float er = (&s_er4[lane].x)[w];
        float e = g_el[n * NHEAD + w] + er;
        e = (e >= 0.0f) ? e : 0.2f * e;                 // leaky relu, slope 0.2
        if (s_mask[lane] == 0) e = NEG_INF;
        float mx = e;
#pragma unroll
        for (int off = 16; off > 0; off >>= 1)
            mx = fmaxf(mx, __shfl_xor_sync(0xffffffffu, mx, off));
        float ex = expf(e - mx);
        float sm = ex;
#pragma unroll
        for (int off = 16; off > 0; off >>= 1)
            sm += __shfl_xor_sync(0xffffffffu, sm, off);
        s_alpha[w][lane] = ex / sm;
    }
    __syncthreads();

    const int hh = tid >> 6;   // head of this channel
    float acc = 0.0f;
#pragma unroll
    for (int m = 0; m < MM; m++) {
        acc = fmaf(s_alpha[hh][m], g_hproj[s_nbr[m] * OUTDIM + tid], acc);
    }

    float x = acc + g_hproj[n * OUTDIM + tid];          // residual
    float g = 0.5f * x * (1.0f + erff(x * 0.70710678118654752f));

    float mean = block_reduce_sum(g, s_red, tid) * (1.0f / 256.0f);
    float d = g - mean;
    float var = block_reduce_sum(d * d, s_red, tid) * (1.0f / 256.0f);
    out[n * OUTDIM + tid] = d * rsqrtf(var + LN_EPS) * gamma[tid] + beta[tid];
}

// ----------------------------------------------------------------------------
extern "C" void kernel_launch(void* const* d_in, const int* in_sizes, int n_in,
                              void* d_out, int out_size) {
    const float* h     = (const float*)d_in[0];
    const int*   nidx  = (const int*)  d_in[1];
    const int*   nmask = (const int*)  d_in[2];
    const float* W     = (const float*)d_in[3];
    const float* a_l   = (const float*)d_in[4];
    const float* a_r   = (const float*)d_in[5];
    const float* gamma = (const float*)d_in[6];
    const float* beta  = (const float*)d_in[7];
    float* out = (float*)d_out;

    dim3 ggrid((NN + 127) / 128, 2);
    gemm_tf32_kernel<<<ggrid, 256>>>(h, W);
    eler_kernel<<<NN, 256>>>(a_l, a_r);
    attn_kernel<<<NN, 256>>>(nidx, nmask, gamma, beta, out);
}

// round 3
// speedup vs baseline: 1.6928x; 1.2104x over previous
#include <cuda_runtime.h>
#include <cuda_fp16.h>
#include <math.h>
#include <stdint.h>

#define NN 20000
#define MM 32
#define INDIM 256
#define OUTDIM 256
#define NHEAD 4
#define HDIM 64
#define LN_EPS 1e-5f
#define NEG_INF -1.0e9f

// scratch buffers
__device__ float    g_hproj[NN * OUTDIM];        // fp32 copy (~20.5 MB)
__device__ uint32_t g_hproj_h2[NN * OUTDIM / 2]; // fp16x2 copy (~10.2 MB) for gather
__device__ float    g_el[NN * NHEAD];
__device__ float    g_er[NN * NHEAD];

// ----------------------------------------------------------------------------
// Kernel 1: h_proj = h @ W  via TF32 mma.sync (m16n8k8), double-buffered.
// Block tile 128x128, BK=16, 256 threads (8 warps: 4M x 2N), warp tile 32x64.
// ----------------------------------------------------------------------------
#define BK 16
#define AS_ST 20
#define BS_ST 132

__device__ __forceinline__ uint32_t f32_to_tf32(float x) {
    uint32_t u;
    asm("cvt.rna.tf32.f32 %0, %1;" : "=r"(u) : "f"(x));
    return u;
}
__device__ __forceinline__ uint4 cvt4(float4 v) {
    uint4 t;
    t.x = f32_to_tf32(v.x); t.y = f32_to_tf32(v.y);
    t.z = f32_to_tf32(v.z); t.w = f32_to_tf32(v.w);
    return t;
}

__device__ __forceinline__ void mma_tf32(float* d, const uint32_t* a, const uint32_t* b) {
    asm volatile(
        "mma.sync.aligned.m16n8k8.row.col.f32.tf32.tf32.f32 "
        "{%0,%1,%2,%3}, {%4,%5,%6,%7}, {%8,%9}, {%0,%1,%2,%3};"
        : "+f"(d[0]), "+f"(d[1]), "+f"(d[2]), "+f"(d[3])
        : "r"(a[0]), "r"(a[1]), "r"(a[2]), "r"(a[3]), "r"(b[0]), "r"(b[1]));
}

__global__ __launch_bounds__(256, 2)
void gemm_tf32_kernel(const float* __restrict__ h, const float* __restrict__ W) {
    __shared__ uint32_t As[2][128 * AS_ST];
    __shared__ uint32_t Bs[2][BK * BS_ST];

    const int tid = threadIdx.x;
    const int lane = tid & 31;
    const int w = tid >> 5;
    const int wm = w & 3;
    const int wn = w >> 2;
    const int m0w = wm * 32;
    const int n0w = wn * 64;

    const int rowBase = blockIdx.x * 128;
    const int nBase = blockIdx.y * 128;

    float acc[2][8][4];
#pragma unroll
    for (int i = 0; i < 2; i++)
#pragma unroll
        for (int j = 0; j < 8; j++)
#pragma unroll
            for (int k = 0; k < 4; k++) acc[i][j][k] = 0.0f;

    const int lr = lane >> 2;
    const int lc = lane & 3;

    // load mappings
    const int a_r0 = tid >> 2;                 // rows a_r0, a_r0+64
    const int a_j  = (tid & 3) * 4;            // k-col
    const int b_k0 = tid >> 5;                 // k rows b_k0, b_k0+8
    const int b_c  = (tid & 31) * 4;           // n-col

    float4 aReg[2], bReg[2];

    // ---- prologue: load tile 0 ----
#pragma unroll
    for (int q = 0; q < 2; q++) {
        int gr = rowBase + a_r0 + 64 * q;
        aReg[q] = (gr < NN) ? *reinterpret_cast<const float4*>(&h[gr * INDIM + a_j])
                            : make_float4(0.f, 0.f, 0.f, 0.f);
        bReg[q] = *reinterpret_cast<const float4*>(&W[(b_k0 + 8 * q) * OUTDIM + nBase + b_c]);
    }
#pragma unroll
    for (int q = 0; q < 2; q++) {
        *reinterpret_cast<uint4*>(&As[0][(a_r0 + 64 * q) * AS_ST + a_j]) = cvt4(aReg[q]);
        *reinterpret_cast<uint4*>(&Bs[0][(b_k0 + 8 * q) * BS_ST + b_c]) = cvt4(bReg[q]);
    }
    __syncthreads();

    const int NITER = INDIM / BK;   // 16
    for (int it = 0; it < NITER; it++) {
        const int stage = it & 1;
        // prefetch next tile into regs
        if (it + 1 < NITER) {
            const int kt = (it + 1) * BK;
#pragma unroll
            for (int q = 0; q < 2; q++) {
                int gr = rowBase + a_r0 + 64 * q;
                aReg[q] = (gr < NN) ? *reinterpret_cast<const float4*>(&h[gr * INDIM + kt + a_j])
                                    : make_float4(0.f, 0.f, 0.f, 0.f);
                bReg[q] = *reinterpret_cast<const float4*>(&W[(kt + b_k0 + 8 * q) * OUTDIM + nBase + b_c]);
            }
        }

        // compute current stage: 2 k-groups of 8
#pragma unroll
        for (int g = 0; g < 2; g++) {
            const int kc = g * 8 + lc;
            uint32_t a[2][4];
#pragma unroll
            for (int tm = 0; tm < 2; tm++) {
                int r = m0w + tm * 16 + lr;
                a[tm][0] = As[stage][r * AS_ST + kc];
                a[tm][1] = As[stage][(r + 8) * AS_ST + kc];
                a[tm][2] = As[stage][r * AS_ST + kc + 4];
                a[tm][3] = As[stage][(r + 8) * AS_ST + kc + 4];
            }
            uint32_t b[8][2];
#pragma unroll
            for (int tn = 0; tn < 8; tn++) {
                int col = n0w + tn * 8 + lr;
                b[tn][0] = Bs[stage][kc * BS_ST + col];
                b[tn][1] = Bs[stage][(kc + 4) * BS_ST + col];
            }
#pragma unroll
            for (int tm = 0; tm < 2; tm++)
#pragma unroll
                for (int tn = 0; tn < 8; tn++)
                    mma_tf32(acc[tm][tn], a[tm], b[tn]);
        }

        if (it + 1 < NITER) {
            __syncthreads();     // all reads of next stage's buffer (iter-1) done
            const int ns = (it + 1) & 1;
#pragma unroll
            for (int q = 0; q < 2; q++) {
                *reinterpret_cast<uint4*>(&As[ns][(a_r0 + 64 * q) * AS_ST + a_j]) = cvt4(aReg[q]);
                *reinterpret_cast<uint4*>(&Bs[ns][(b_k0 + 8 * q) * BS_ST + b_c]) = cvt4(bReg[q]);
            }
            __syncthreads();
        }
    }

    // ---- epilogue: fp32 + fp16x2 stores ----
#pragma unroll
    for (int tm = 0; tm < 2; tm++) {
#pragma unroll
        for (int tn = 0; tn < 8; tn++) {
            int gr0 = rowBase + m0w + tm * 16 + lr;
            int gc = nBase + n0w + tn * 8 + 2 * lc;
            if (gr0 < NN) {
                *reinterpret_cast<float2*>(&g_hproj[gr0 * OUTDIM + gc]) =
                    make_float2(acc[tm][tn][0], acc[tm][tn][1]);
                __half2 hh = __float22half2_rn(make_float2(acc[tm][tn][0], acc[tm][tn][1]));
                g_hproj_h2[gr0 * (OUTDIM / 2) + (gc >> 1)] = *reinterpret_cast<uint32_t*>(&hh);
            }
            if (gr0 + 8 < NN) {
                *reinterpret_cast<float2*>(&g_hproj[(gr0 + 8) * OUTDIM + gc]) =
                    make_float2(acc[tm][tn][2], acc[tm][tn][3]);
                __half2 hh = __float22half2_rn(make_float2(acc[tm][tn][2], acc[tm][tn][3]));
                g_hproj_h2[(gr0 + 8) * (OUTDIM / 2) + (gc >> 1)] = *reinterpret_cast<uint32_t*>(&hh);
            }
        }
    }
}

// ----------------------------------------------------------------------------
// Kernel 2: el/er dot products. One block (256 threads) per node.
// ----------------------------------------------------------------------------
__global__ __launch_bounds__(256)
void eler_kernel(const float* __restrict__ a_l, const float* __restrict__ a_r) {
    const int n = blockIdx.x;
    const int c = threadIdx.x;
    float hp = g_hproj[n * OUTDIM + c];
    float pl = hp * a_l[c];
    float pr = hp * a_r[c];
#pragma unroll
    for (int off = 16; off > 0; off >>= 1) {
        pl += __shfl_xor_sync(0xffffffffu, pl, off);
        pr += __shfl_xor_sync(0xffffffffu, pr, off);
    }
    __shared__ float sl[8], sr[8];
    if ((c & 31) == 0) { sl[c >> 5] = pl; sr[c >> 5] = pr; }
    __syncthreads();
    if (c < NHEAD) {
        g_el[n * NHEAD + c] = sl[2 * c] + sl[2 * c + 1];
        g_er[n * NHEAD + c] = sr[2 * c] + sr[2 * c + 1];
    }
}

// ----------------------------------------------------------------------------
// Kernel 3: attention + residual + GELU + LayerNorm.
// 128 threads per node; each thread owns channel pair (2t, 2t+1); head == warp.
// ----------------------------------------------------------------------------
__global__ __launch_bounds__(128)
void attn_kernel(const int* __restrict__ nidx, const int* __restrict__ nmask,
                 const float* __restrict__ gamma, const float* __restrict__ beta,
                 float* __restrict__ out) {
    const int n = blockIdx.x;
    const int tid = threadIdx.x;
    const int w = tid >> 5;           // warp == head == channel-pair group
    const int lane = tid & 31;

    __shared__ float  s_alpha[NHEAD][MM];
    __shared__ int    s_nbr[MM];
    __shared__ int    s_mask[MM];
    __shared__ float4 s_er4[MM];
    __shared__ float  s_red[2][4];

    if (w == 0) {
        int nb = nidx[n * MM + lane];
        s_nbr[lane] = nb;
        s_mask[lane] = nmask[n * MM + lane];
        s_er4[lane] = *reinterpret_cast<const float4*>(&g_er[nb * NHEAD]);
    }
    __syncthreads();

    // softmax: warp w handles head w over 32 neighbors (lane = m)
    {
        float er = (&s_er4[lane].x)[w];
        float e = g_el[n * NHEAD + w] + er;
        e = (e >= 0.0f) ? e : 0.2f * e;
        if (s_mask[lane] == 0) e = NEG_INF;
        float mx = e;
#pragma unroll
        for (int off = 16; off > 0; off >>= 1)
            mx = fmaxf(mx, __shfl_xor_sync(0xffffffffu, mx, off));
        float ex = expf(e - mx);
        float sm = ex;
#pragma unroll
        for (int off = 16; off > 0; off >>= 1)
            sm += __shfl_xor_sync(0xffffffffu, sm, off);
        s_alpha[w][lane] = ex / sm;
    }
    __syncthreads();

    // gather: fp16x2 rows
    float ax = 0.0f, ay = 0.0f;
#pragma unroll
    for (int m = 0; m < MM; m++) {
        uint32_t v = g_hproj_h2[s_nbr[m] * (OUTDIM / 2) + tid];
        __half2 hv = *reinterpret_cast<__half2*>(&v);
        float2 f = __half22float2(hv);
        float al = s_alpha[w][m];
        ax = fmaf(al, f.x, ax);
        ay = fmaf(al, f.y, ay);
    }

    // residual + exact GELU
    float2 res = *reinterpret_cast<const float2*>(&g_hproj[n * OUTDIM + 2 * tid]);
    float x0 = ax + res.x;
    float x1 = ay + res.y;
    float g0 = 0.5f * x0 * (1.0f + erff(x0 * 0.70710678118654752f));
    float g1 = 0.5f * x1 * (1.0f + erff(x1 * 0.70710678118654752f));

    // LayerNorm: single pass (sum, sumsq)
    float s1 = g0 + g1;
    float s2 = g0 * g0 + g1 * g1;
#pragma unroll
    for (int off = 16; off > 0; off >>= 1) {
        s1 += __shfl_xor_sync(0xffffffffu, s1, off);
        s2 += __shfl_xor_sync(0xffffffffu, s2, off);
    }
    if (lane == 0) { s_red[0][w] = s1; s_red[1][w] = s2; }
    __syncthreads();
    float S1 = s_red[0][0] + s_red[0][1] + s_red[0][2] + s_red[0][3];
    float S2 = s_red[1][0] + s_red[1][1] + s_red[1][2] + s_red[1][3];
    float mean = S1 * (1.0f / 256.0f);
    float var = S2 * (1.0f / 256.0f) - mean * mean;
    float inv = rsqrtf(var + LN_EPS);

    float2 gm = *reinterpret_cast<const float2*>(&gamma[2 * tid]);
    float2 bt = *reinterpret_cast<const float2*>(&beta[2 * tid]);
    float o0 = (g0 - mean) * inv * gm.x + bt.x;
    float o1 = (g1 - mean) * inv * gm.y + bt.y;
    *reinterpret_cast<float2*>(&out[n * OUTDIM + 2 * tid]) = make_float2(o0, o1);
}

// ----------------------------------------------------------------------------
extern "C" void kernel_launch(void* const* d_in, const int* in_sizes, int n_in,
                              void* d_out, int out_size) {
    const float* h     = (const float*)d_in[0];
    const int*   nidx  = (const int*)  d_in[1];
    const int*   nmask = (const int*)  d_in[2];
    const float* W     = (const float*)d_in[3];
    const float* a_l   = (const float*)d_in[4];
    const float* a_r   = (const float*)d_in[5];
    const float* gamma = (const float*)d_in[6];
    const float* beta  = (const float*)d_in[7];
    float* out = (float*)d_out;

    dim3 ggrid((NN + 127) / 128, 2);
    gemm_tf32_kernel<<<ggrid, 256>>>(h, W);
    eler_kernel<<<NN, 256>>>(a_l, a_r);
    attn_kernel<<<NN, 128>>>(nidx, nmask, gamma, beta, out);
}

// round 4
// speedup vs baseline: 1.9846x; 1.1724x over previous
#include <cuda_runtime.h>
#include <cuda_fp16.h>
#include <math.h>
#include <stdint.h>

#define NN 20000
#define MM 32
#define INDIM 256
#define OUTDIM 256
#define NHEAD 4
#define HDIM 64
#define LN_EPS 1e-5f
#define NEG_INF -1.0e9f

// scratch buffers
__device__ float    g_hproj[NN * OUTDIM];        // fp32 copy (~20.5 MB)
__device__ uint32_t g_hproj_h2[NN * OUTDIM / 2]; // fp16x2 copy (~10.2 MB) for gather
__device__ float    g_el[NN * NHEAD];
__device__ float    g_er[NN * NHEAD];

// ----------------------------------------------------------------------------
// Kernel 1: h_proj = h @ W via TF32 mma.sync, cp.async 3-stage pipeline.
// Block tile 128x128, BK=32, 256 threads (8 warps: 4M x 2N), warp tile 32x64.
// Raw fp32 staged in smem; cvt.rna.tf32 at fragment load.
// ----------------------------------------------------------------------------
#define BK 32
#define AS_ST 36            // words per A row (32 + 4 pad)
#define BS_ST 132           // words per B row (128 + 4 pad)
#define A_WORDS (128 * AS_ST)
#define STAGE_WORDS (A_WORDS + BK * BS_ST)   // 8832
#define NSTAGE 3
#define GEMM_SMEM_BYTES (NSTAGE * STAGE_WORDS * 4)  // 105984

__device__ __forceinline__ uint32_t f32_to_tf32(float x) {
    uint32_t u;
    asm("cvt.rna.tf32.f32 %0, %1;" : "=r"(u) : "f"(x));
    return u;
}

__device__ __forceinline__ void mma_tf32(float* d, const uint32_t* a, const uint32_t* b) {
    asm volatile(
        "mma.sync.aligned.m16n8k8.row.col.f32.tf32.tf32.f32 "
        "{%0,%1,%2,%3}, {%4,%5,%6,%7}, {%8,%9}, {%0,%1,%2,%3};"
        : "+f"(d[0]), "+f"(d[1]), "+f"(d[2]), "+f"(d[3])
        : "r"(a[0]), "r"(a[1]), "r"(a[2]), "r"(a[3]), "r"(b[0]), "r"(b[1]));
}

__device__ __forceinline__ void cp_async16(uint32_t dst, const void* src, int src_bytes) {
    asm volatile("cp.async.cg.shared.global [%0], [%1], 16, %2;\n"
                 :: "r"(dst), "l"(src), "r"(src_bytes));
}
__device__ __forceinline__ void cp_commit() {
    asm volatile("cp.async.commit_group;\n" ::: "memory");
}
template <int N>
__device__ __forceinline__ void cp_wait() {
    asm volatile("cp.async.wait_group %0;\n" :: "n"(N) : "memory");
}

__global__ __launch_bounds__(256, 2)
void gemm_tf32_kernel(const float* __restrict__ h, const float* __restrict__ W) {
    extern __shared__ uint32_t dyns[];
    const uint32_t smem_base = (uint32_t)__cvta_generic_to_shared(dyns);

    const int tid = threadIdx.x;
    const int lane = tid & 31;
    const int w = tid >> 5;
    const int wm = w & 3;
    const int wn = w >> 2;
    const int m0w = wm * 32;
    const int n0w = wn * 64;

    const int rowBase = blockIdx.x * 128;
    const int nBase = blockIdx.y * 128;

    // copy mappings: A tile 128x32 (4 float4/thread), B tile 32x128 (4 float4/thread)
    const int a_r = tid >> 3;             // +32 per q : rows a_r, a_r+32, a_r+64, a_r+96
    const int a_c = (tid & 7) * 4;        // k offset (floats)
    const int b_k = tid >> 5;             // +8 per q
    const int b_c = (tid & 31) * 4;       // n offset (floats)

    auto issue_copies = [&](int stage, int kt) {
        uint32_t aBase = smem_base + (stage * STAGE_WORDS) * 4;
        uint32_t bBase = aBase + A_WORDS * 4;
#pragma unroll
        for (int q = 0; q < 4; q++) {
            int r = a_r + 32 * q;
            int gr = rowBase + r;
            int sz = (gr < NN) ? 16 : 0;
            cp_async16(aBase + (r * AS_ST + a_c) * 4, &h[gr * INDIM + kt + a_c], sz);
        }
#pragma unroll
        for (int q = 0; q < 4; q++) {
            int k = b_k + 8 * q;
            cp_async16(bBase + (k * BS_ST + b_c) * 4, &W[(kt + k) * OUTDIM + nBase + b_c], 16);
        }
    };

    float acc[2][8][4];
#pragma unroll
    for (int i = 0; i < 2; i++)
#pragma unroll
        for (int j = 0; j < 8; j++)
#pragma unroll
            for (int k = 0; k < 4; k++) acc[i][j][k] = 0.0f;

    const int lr = lane >> 2;
    const int lc = lane & 3;

    // prologue: stages 0 and 1 in flight
    issue_copies(0, 0);
    cp_commit();
    issue_copies(1, BK);
    cp_commit();

    const int NITER = INDIM / BK;   // 8
    for (int it = 0; it < NITER; it++) {
        cp_wait<1>();          // this thread's stage-it group done
        __syncthreads();       // all threads' groups done -> stage resident; prior reads of overwrite target done

        const uint32_t* As = dyns + (it % NSTAGE) * STAGE_WORDS;
        const uint32_t* Bs = As + A_WORDS;

        // compute: 4 k-groups of 8
#pragma unroll
        for (int g = 0; g < 4; g++) {
            const int kc = g * 8 + lc;
            uint32_t a[2][4];
#pragma unroll
            for (int tm = 0; tm < 2; tm++) {
                int r = m0w + tm * 16 + lr;
                a[tm][0] = f32_to_tf32(__uint_as_float(As[r * AS_ST + kc]));
                a[tm][1] = f32_to_tf32(__uint_as_float(As[(r + 8) * AS_ST + kc]));
                a[tm][2] = f32_to_tf32(__uint_as_float(As[r * AS_ST + kc + 4]));
                a[tm][3] = f32_to_tf32(__uint_as_float(As[(r + 8) * AS_ST + kc + 4]));
            }
            uint32_t b[8][2];
#pragma unroll
            for (int tn = 0; tn < 8; tn++) {
                int col = n0w + tn * 8 + lr;
                b[tn][0] = f32_to_tf32(__uint_as_float(Bs[kc * BS_ST + col]));
                b[tn][1] = f32_to_tf32(__uint_as_float(Bs[(kc + 4) * BS_ST + col]));
            }
#pragma unroll
            for (int tm = 0; tm < 2; tm++)
#pragma unroll
                for (int tn = 0; tn < 8; tn++)
                    mma_tf32(acc[tm][tn], a[tm], b[tn]);
        }

        // launch copies for stage it+2 (overwrites buffer last read in iter it-1)
        if (it + 2 < NITER)
            issue_copies((it + 2) % NSTAGE, (it + 2) * BK);
        cp_commit();
    }

    // ---- epilogue: fp32 + fp16x2 stores ----
#pragma unroll
    for (int tm = 0; tm < 2; tm++) {
#pragma unroll
        for (int tn = 0; tn < 8; tn++) {
            int gr0 = rowBase + m0w + tm * 16 + lr;
            int gc = nBase + n0w + tn * 8 + 2 * lc;
            if (gr0 < NN) {
                *reinterpret_cast<float2*>(&g_hproj[gr0 * OUTDIM + gc]) =
                    make_float2(acc[tm][tn][0], acc[tm][tn][1]);
                __half2 hh = __float22half2_rn(make_float2(acc[tm][tn][0], acc[tm][tn][1]));
                g_hproj_h2[gr0 * (OUTDIM / 2) + (gc >> 1)] = *reinterpret_cast<uint32_t*>(&hh);
            }
            if (gr0 + 8 < NN) {
                *reinterpret_cast<float2*>(&g_hproj[(gr0 + 8) * OUTDIM + gc]) =
                    make_float2(acc[tm][tn][2], acc[tm][tn][3]);
                __half2 hh = __float22half2_rn(make_float2(acc[tm][tn][2], acc[tm][tn][3]));
                g_hproj_h2[(gr0 + 8) * (OUTDIM / 2) + (gc >> 1)] = *reinterpret_cast<uint32_t*>(&hh);
            }
        }
    }
}

// ----------------------------------------------------------------------------
// Kernel 2: el/er dot products. One warp per node, 8 nodes per block.
// ----------------------------------------------------------------------------
__global__ __launch_bounds__(256)
void eler_kernel(const float* __restrict__ a_l, const float* __restrict__ a_r) {
    const int node = blockIdx.x * 8 + (threadIdx.x >> 5);
    if (node >= NN) return;
    const int lane = threadIdx.x & 31;

    const float4* hp4 = reinterpret_cast<const float4*>(&g_hproj[node * OUTDIM + lane * 8]);
    float4 v0 = hp4[0], v1 = hp4[1];
    const float4* al4 = reinterpret_cast<const float4*>(&a_l[lane * 8]);
    const float4* ar4 = reinterpret_cast<const float4*>(&a_r[lane * 8]);
    float4 l0 = al4[0], l1 = al4[1];
    float4 r0 = ar4[0], r1 = ar4[1];

    float pl = v0.x * l0.x + v0.y * l0.y + v0.z * l0.z + v0.w * l0.w
             + v1.x * l1.x + v1.y * l1.y + v1.z * l1.z + v1.w * l1.w;
    float pr = v0.x * r0.x + v0.y * r0.y + v0.z * r0.z + v0.w * r0.w
             + v1.x * r1.x + v1.y * r1.y + v1.z * r1.z + v1.w * r1.w;

#pragma unroll
    for (int off = 4; off >= 1; off >>= 1) {
        pl += __shfl_down_sync(0xffffffffu, pl, off);
        pr += __shfl_down_sync(0xffffffffu, pr, off);
    }
    if ((lane & 7) == 0) {
        int hh = lane >> 3;
        g_el[node * NHEAD + hh] = pl;
        g_er[node * NHEAD + hh] = pr;
    }
}

// ----------------------------------------------------------------------------
// Kernel 3: attention + residual + GELU + LayerNorm. 128 threads per node.
// Gather phase: one warp covers a full 512B fp16 row (uint4/lane); each warp
// handles 8 of the 32 neighbors; partials reduced through smem.
// ----------------------------------------------------------------------------
__global__ __launch_bounds__(128)
void attn_kernel(const int* __restrict__ nidx, const int* __restrict__ nmask,
                 const float* __restrict__ gamma, const float* __restrict__ beta,
                 float* __restrict__ out) {
    const int n = blockIdx.x;
    const int tid = threadIdx.x;
    const int w = tid >> 5;           // warp id (= head for softmax phase)
    const int lane = tid & 31;

    __shared__ float  s_alpha[NHEAD][MM];
    __shared__ int    s_nbr[MM];
    __shared__ int    s_mask[MM];
    __shared__ float4 s_er4[MM];
    __shared__ float  s_part[NHEAD][OUTDIM];
    __shared__ float  s_red[2][NHEAD];

    if (w == 0) {
        int nb = nidx[n * MM + lane];
        s_nbr[lane] = nb;
        s_mask[lane] = nmask[n * MM + lane];
        s_er4[lane] = *reinterpret_cast<const float4*>(&g_er[nb * NHEAD]);
    }
    __syncthreads();

    // softmax: warp w = head w over 32 neighbors (lane = m)
    {
        float er = (&s_er4[lane].x)[w];
        float e = g_el[n * NHEAD + w] + er;
        e = (e >= 0.0f) ? e : 0.2f * e;
        if (s_mask[lane] == 0) e = NEG_INF;
        float mx = e;
#pragma unroll
        for (int off = 16; off > 0; off >>= 1)
            mx = fmaxf(mx, __shfl_xor_sync(0xffffffffu, mx, off));
        float ex = expf(e - mx);
        float sm = ex;
#pragma unroll
        for (int off = 16; off > 0; off >>= 1)
            sm += __shfl_xor_sync(0xffffffffu, sm, off);
        s_alpha[w][lane] = ex / sm;
    }
    __syncthreads();

    // gather: lane covers channels 8*lane .. 8*lane+7 ; warp w does m = 4i+w
    const int hh = lane >> 3;         // head of this lane's channels
    float acc[8];
#pragma unroll
    for (int j = 0; j < 8; j++) acc[j] = 0.0f;

#pragma unroll
    for (int i = 0; i < 8; i++) {
        int m = i * 4 + w;
        int row = s_nbr[m];
        float al = s_alpha[hh][m];
        uint4 v = *reinterpret_cast<const uint4*>(&g_hproj_h2[row * (OUTDIM / 2) + lane * 4]);
        float2 f0 = __half22float2(*reinterpret_cast<__half2*>(&v.x));
        float2 f1 = __half22float2(*reinterpret_cast<__half2*>(&v.y));
        float2 f2 = __half22float2(*reinterpret_cast<__half2*>(&v.z));
        float2 f3 = __half22float2(*reinterpret_cast<__half2*>(&v.w));
        acc[0] = fmaf(al, f0.x, acc[0]); acc[1] = fmaf(al, f0.y, acc[1]);
        acc[2] = fmaf(al, f1.x, acc[2]); acc[3] = fmaf(al, f1.y, acc[3]);
        acc[4] = fmaf(al, f2.x, acc[4]); acc[5] = fmaf(al, f2.y, acc[5]);
        acc[6] = fmaf(al, f3.x, acc[6]); acc[7] = fmaf(al, f3.y, acc[7]);
    }
    *reinterpret_cast<float4*>(&s_part[w][lane * 8])     = make_float4(acc[0], acc[1], acc[2], acc[3]);
    *reinterpret_cast<float4*>(&s_part[w][lane * 8 + 4]) = make_float4(acc[4], acc[5], acc[6], acc[7]);
    __syncthreads();

    // final: thread owns channels 2*tid, 2*tid+1
    const int c = 2 * tid;
    float2 p0 = *reinterpret_cast<const float2*>(&s_part[0][c]);
    float2 p1 = *reinterpret_cast<const float2*>(&s_part[1][c]);
    float2 p2 = *reinterpret_cast<const float2*>(&s_part[2][c]);
    float2 p3 = *reinterpret_cast<const float2*>(&s_part[3][c]);
    float ax = p0.x + p1.x + p2.x + p3.x;
    float ay = p0.y + p1.y + p2.y + p3.y;

    float2 res = *reinterpret_cast<const float2*>(&g_hproj[n * OUTDIM + c]);
    float x0 = ax + res.x;
    float x1 = ay + res.y;
    float g0 = 0.5f * x0 * (1.0f + erff(x0 * 0.70710678118654752f));
    float g1 = 0.5f * x1 * (1.0f + erff(x1 * 0.70710678118654752f));

    float s1 = g0 + g1;
    float s2 = g0 * g0 + g1 * g1;
#pragma unroll
    for (int off = 16; off > 0; off >>= 1) {
        s1 += __shfl_xor_sync(0xffffffffu, s1, off);
        s2 += __shfl_xor_sync(0xffffffffu, s2, off);
    }
    if (lane == 0) { s_red[0][w] = s1; s_red[1][w] = s2; }
    __syncthreads();
    float S1 = s_red[0][0] + s_red[0][1] + s_red[0][2] + s_red[0][3];
    float S2 = s_red[1][0] + s_red[1][1] + s_red[1][2] + s_red[1][3];
    float mean = S1 * (1.0f / 256.0f);
    float var = S2 * (1.0f / 256.0f) - mean * mean;
    float inv = rsqrtf(var + LN_EPS);

    float2 gm = *reinterpret_cast<const float2*>(&gamma[c]);
    float2 bt = *reinterpret_cast<const float2*>(&beta[c]);
    float o0 = (g0 - mean) * inv * gm.x + bt.x;
    float o1 = (g1 - mean) * inv * gm.y + bt.y;
    *reinterpret_cast<float2*>(&out[n * OUTDIM + c]) = make_float2(o0, o1);
}

// ----------------------------------------------------------------------------
extern "C" void kernel_launch(void* const* d_in, const int* in_sizes, int n_in,
                              void* d_out, int out_size) {
    const float* h     = (const float*)d_in[0];
    const int*   nidx  = (const int*)  d_in[1];
    const int*   nmask = (const int*)  d_in[2];
    const float* W     = (const float*)d_in[3];
    const float* a_l   = (const float*)d_in[4];
    const float* a_r   = (const float*)d_in[5];
    const float* gamma = (const float*)d_in[6];
    const float* beta  = (const float*)d_in[7];
    float* out = (float*)d_out;

    cudaFuncSetAttribute(gemm_tf32_kernel,
                         cudaFuncAttributeMaxDynamicSharedMemorySize, GEMM_SMEM_BYTES);

    dim3 ggrid((NN + 127) / 128, 2);
    gemm_tf32_kernel<<<ggrid, 256, GEMM_SMEM_BYTES>>>(h, W);
    eler_kernel<<<(NN + 7) / 8, 256>>>(a_l, a_r);
    attn_kernel<<<NN, 128>>>(nidx, nmask, gamma, beta, out);
}

// round 5
// speedup vs baseline: 2.3906x; 1.2046x over previous
#include <cuda_runtime.h>
#include <cuda_fp16.h>
#include <math.h>
#include <stdint.h>

#define NN 20000
#define MM 32
#define INDIM 256
#define OUTDIM 256
#define NHEAD 4
#define HDIM 64
#define LN_EPS 1e-5f
#define NEG_INF -1.0e9f

// scratch buffers (all fp16 pairs packed in uint32)
__device__ uint32_t g_h16[NN * INDIM / 2];        // fp16 copy of input h (~10.2 MB)
__device__ uint32_t g_W16[INDIM * OUTDIM / 2];    // fp16 copy of W (128 KB)
__device__ uint32_t g_hproj_h2[NN * OUTDIM / 2];  // fp16 h_proj (~10.2 MB)
__device__ float    g_el[NN * NHEAD];
__device__ float    g_er[NN * NHEAD];

// ----------------------------------------------------------------------------
// Kernel 0: convert h and W to fp16.
// ----------------------------------------------------------------------------
#define NH4 (NN * INDIM / 4)
#define NW4 (INDIM * OUTDIM / 4)

__global__ __launch_bounds__(256)
void convert_kernel(const float* __restrict__ h, const float* __restrict__ W) {
    int stride = gridDim.x * blockDim.x;
    for (int i = blockIdx.x * blockDim.x + threadIdx.x; i < NH4 + NW4; i += stride) {
        float4 v;
        uint32_t* dst;
        if (i < NH4) {
            v = reinterpret_cast<const float4*>(h)[i];
            dst = &g_h16[i * 2];
        } else {
            v = reinterpret_cast<const float4*>(W)[i - NH4];
            dst = &g_W16[(i - NH4) * 2];
        }
        __half2 a = __float22half2_rn(make_float2(v.x, v.y));
        __half2 b = __float22half2_rn(make_float2(v.z, v.w));
        dst[0] = *reinterpret_cast<uint32_t*>(&a);
        dst[1] = *reinterpret_cast<uint32_t*>(&b);
    }
}

// ----------------------------------------------------------------------------
// Kernel 1: h_proj = h @ W, fp16 mma.sync m16n8k16, 4-stage cp.async, ldmatrix.
// Block tile 128x64, BK=32, 256 threads (8 warps: 4M x 2N), warp tile 32x32.
// A smem row stride 40 halves (80B), B stride 72 halves (144B): both give
// bank-disjoint 16B chunks across 8 consecutive rows -> conflict-free ldmatrix.
// ----------------------------------------------------------------------------
#define BKG 32
#define A_ST 40                      // halves per A row
#define B_ST 72                      // halves per B row
#define A_HALFS (128 * A_ST)         // 5120
#define B_HALFS (BKG * B_ST)         // 2304
#define STAGE_BYTES ((A_HALFS + B_HALFS) * 2)   // 14848
#define NSTG 4
#define GEMM_SMEM_BYTES (NSTG * STAGE_BYTES)    // 59392

__device__ __forceinline__ void cp_async16(uint32_t dst, const void* src, int src_bytes) {
    asm volatile("cp.async.cg.shared.global [%0], [%1], 16, %2;\n"
                 :: "r"(dst), "l"(src), "r"(src_bytes));
}
__device__ __forceinline__ void cp_commit() {
    asm volatile("cp.async.commit_group;\n" ::: "memory");
}
template <int N>
__device__ __forceinline__ void cp_wait() {
    asm volatile("cp.async.wait_group %0;\n" :: "n"(N) : "memory");
}
__device__ __forceinline__ void ldsm_x4(uint32_t& r0, uint32_t& r1, uint32_t& r2,
                                        uint32_t& r3, uint32_t addr) {
    asm volatile("ldmatrix.sync.aligned.m8n8.x4.shared.b16 {%0,%1,%2,%3}, [%4];"
                 : "=r"(r0), "=r"(r1), "=r"(r2), "=r"(r3) : "r"(addr));
}
__device__ __forceinline__ void ldsm_x4_t(uint32_t& r0, uint32_t& r1, uint32_t& r2,
                                          uint32_t& r3, uint32_t addr) {
    asm volatile("ldmatrix.sync.aligned.m8n8.x4.trans.shared.b16 {%0,%1,%2,%3}, [%4];"
                 : "=r"(r0), "=r"(r1), "=r"(r2), "=r"(r3) : "r"(addr));
}
__device__ __forceinline__ void mma_f16(float* d, const uint32_t* a, const uint32_t* b) {
    asm volatile(
        "mma.sync.aligned.m16n8k16.row.col.f32.f16.f16.f32 "
        "{%0,%1,%2,%3}, {%4,%5,%6,%7}, {%8,%9}, {%0,%1,%2,%3};"
        : "+f"(d[0]), "+f"(d[1]), "+f"(d[2]), "+f"(d[3])
        : "r"(a[0]), "r"(a[1]), "r"(a[2]), "r"(a[3]), "r"(b[0]), "r"(b[1]));
}

__global__ __launch_bounds__(256, 3)
void gemm_f16_kernel() {
    extern __shared__ uint8_t dynsm[];
    const uint32_t smem_base = (uint32_t)__cvta_generic_to_shared(dynsm);

    const int tid = threadIdx.x;
    const int lane = tid & 31;
    const int w = tid >> 5;
    const int wm = w & 3;            // 4 M-subtiles of 32
    const int wn = w >> 2;           // 2 N-subtiles of 32
    const int m0w = wm * 32;
    const int n0w = wn * 32;

    const int rowBase = blockIdx.x * 128;
    const int nBase = blockIdx.y * 64;

    // cp.async mappings (halves -> uint32 words in g_h16/g_W16)
    const int a_row0 = tid >> 2;           // +64 per q (2 chunks/thread)
    const int a_ch   = (tid & 3) * 8;      // half offset within row
    const int b_row  = tid >> 3;           // 0..31
    const int b_ch   = (tid & 7) * 8;      // half offset

    auto issue_copies = [&](int stage, int kt) {
        uint32_t aB = smem_base + stage * STAGE_BYTES;
        uint32_t bB = aB + A_HALFS * 2;
#pragma unroll
        for (int q = 0; q < 2; q++) {
            int r = a_row0 + 64 * q;
            int gr = rowBase + r;
            int sz = (gr < NN) ? 16 : 0;
            cp_async16(aB + (r * A_ST + a_ch) * 2,
                       &g_h16[(gr * INDIM + kt + a_ch) >> 1], sz);
        }
        cp_async16(bB + (b_row * B_ST + b_ch) * 2,
                   &g_W16[((kt + b_row) * OUTDIM + nBase + b_ch) >> 1], 16);
    };

    float acc[2][4][4];
#pragma unroll
    for (int i = 0; i < 2; i++)
#pragma unroll
        for (int j = 0; j < 4; j++)
#pragma unroll
            for (int k = 0; k < 4; k++) acc[i][j][k] = 0.0f;

    // ldmatrix lane offsets
    const int r8 = lane & 7;
    const int quad = lane >> 3;
    const int qRow = (quad & 1) << 3;      // 0 or 8
    const int qCol = (quad >> 1) << 3;     // 0 or 8

    // prologue: 3 stages in flight
    issue_copies(0, 0);  cp_commit();
    issue_copies(1, BKG); cp_commit();
    issue_copies(2, 2 * BKG); cp_commit();

    const int NITER = INDIM / BKG;  // 8
    for (int it = 0; it < NITER; it++) {
        cp_wait<2>();
        __syncthreads();
        const uint32_t sA = smem_base + (it & (NSTG - 1)) * STAGE_BYTES;
        const uint32_t sB = sA + A_HALFS * 2;

#pragma unroll
        for (int g = 0; g < 2; g++) {
            const int k0 = g * 16;
            uint32_t a[2][4];
#pragma unroll
            for (int tm = 0; tm < 2; tm++) {
                uint32_t addr = sA + ((m0w + tm * 16 + qRow + r8) * A_ST + k0 + qCol) * 2;
                ldsm_x4(a[tm][0], a[tm][1], a[tm][2], a[tm][3], addr);
            }
            uint32_t b[2][4];
#pragma unroll
            for (int t2 = 0; t2 < 2; t2++) {
                uint32_t addr = sB + ((k0 + qRow + r8) * B_ST + n0w + t2 * 16 + qCol) * 2;
                ldsm_x4_t(b[t2][0], b[t2][1], b[t2][2], b[t2][3], addr);
            }
#pragma unroll
            for (int tm = 0; tm < 2; tm++)
#pragma unroll
                for (int tn = 0; tn < 4; tn++) {
                    uint32_t bb[2] = { b[tn >> 1][2 * (tn & 1)], b[tn >> 1][2 * (tn & 1) + 1] };
                    mma_f16(acc[tm][tn], a[tm], bb);
                }
        }

        if (it + 3 < NITER)
            issue_copies((it + 3) & (NSTG - 1), (it + 3) * BKG);
        cp_commit();   // unconditional: keeps wait_group accounting correct
    }

    // epilogue: fp16 stores only
    const int lr = lane >> 2;
    const int lc = lane & 3;
#pragma unroll
    for (int tm = 0; tm < 2; tm++) {
#pragma unroll
        for (int tn = 0; tn < 4; tn++) {
            int row0 = rowBase + m0w + tm * 16 + lr;
            int col = nBase + n0w + tn * 8 + 2 * lc;
            if (row0 < NN) {
                __half2 v = __float22half2_rn(make_float2(acc[tm][tn][0], acc[tm][tn][1]));
                g_hproj_h2[(row0 * OUTDIM + col) >> 1] = *reinterpret_cast<uint32_t*>(&v);
            }
            if (row0 + 8 < NN) {
                __half2 v = __float22half2_rn(make_float2(acc[tm][tn][2], acc[tm][tn][3]));
                g_hproj_h2[((row0 + 8) * OUTDIM + col) >> 1] = *reinterpret_cast<uint32_t*>(&v);
            }
        }
    }
}

// ----------------------------------------------------------------------------
// Kernel 2: el/er dot products from fp16 h_proj. One warp per node.
// ----------------------------------------------------------------------------
__global__ __launch_bounds__(256)
void eler_kernel(const float* __restrict__ a_l, const float* __restrict__ a_r) {
    const int node = blockIdx.x * 8 + (threadIdx.x >> 5);
    if (node >= NN) return;
    const int lane = threadIdx.x & 31;

    uint4 v = *reinterpret_cast<const uint4*>(&g_hproj_h2[node * (OUTDIM / 2) + lane * 4]);
    float2 f0 = __half22float2(*reinterpret_cast<__half2*>(&v.x));
    float2 f1 = __half22float2(*reinterpret_cast<__half2*>(&v.y));
    float2 f2 = __half22float2(*reinterpret_cast<__half2*>(&v.z));
    float2 f3 = __half22float2(*reinterpret_cast<__half2*>(&v.w));

    const float4* al4 = reinterpret_cast<const float4*>(&a_l[lane * 8]);
    const float4* ar4 = reinterpret_cast<const float4*>(&a_r[lane * 8]);
    float4 l0 = al4[0], l1 = al4[1];
    float4 r0 = ar4[0], r1 = ar4[1];

    float pl = f0.x * l0.x + f0.y * l0.y + f1.x * l0.z + f1.y * l0.w
             + f2.x * l1.x + f2.y * l1.y + f3.x * l1.z + f3.y * l1.w;
    float pr = f0.x * r0.x + f0.y * r0.y + f1.x * r0.z + f1.y * r0.w
             + f2.x * r1.x + f2.y * r1.y + f3.x * r1.z + f3.y * r1.w;

#pragma unroll
    for (int off = 4; off >= 1; off >>= 1) {
        pl += __shfl_down_sync(0xffffffffu, pl, off);
        pr += __shfl_down_sync(0xffffffffu, pr, off);
    }
    if ((lane & 7) == 0) {
        int hh = lane >> 3;
        g_el[node * NHEAD + hh] = pl;
        g_er[node * NHEAD + hh] = pr;
    }
}

// ----------------------------------------------------------------------------
// Kernel 3: attention + residual + GELU + LayerNorm. 128 threads per node.
// ----------------------------------------------------------------------------
__global__ __launch_bounds__(128)
void attn_kernel(const int* __restrict__ nidx, const int* __restrict__ nmask,
                 const float* __restrict__ gamma, const float* __restrict__ beta,
                 float* __restrict__ out) {
    const int n = blockIdx.x;
    const int tid = threadIdx.x;
    const int w = tid >> 5;
    const int lane = tid & 31;

    __shared__ float  s_alpha[NHEAD][MM];
    __shared__ int    s_nbr[MM];
    __shared__ int    s_mask[MM];
    __shared__ float4 s_er4[MM];
    __shared__ float  s_part[NHEAD][OUTDIM];
    __shared__ float  s_red[2][NHEAD];

    if (w == 0) {
        int nb = nidx[n * MM + lane];
        s_nbr[lane] = nb;
        s_mask[lane] = nmask[n * MM + lane];
        s_er4[lane] = *reinterpret_cast<const float4*>(&g_er[nb * NHEAD]);
    }
    __syncthreads();

    // softmax: warp w = head w over 32 neighbors (lane = m)
    {
        float er = (&s_er4[lane].x)[w];
        float e = g_el[n * NHEAD + w] + er;
        e = (e >= 0.0f) ? e : 0.2f * e;
        if (s_mask[lane] == 0) e = NEG_INF;
        float mx = e;
#pragma unroll
        for (int off = 16; off > 0; off >>= 1)
            mx = fmaxf(mx, __shfl_xor_sync(0xffffffffu, mx, off));
        float ex = expf(e - mx);
        float sm = ex;
#pragma unroll
        for (int off = 16; off > 0; off >>= 1)
            sm += __shfl_xor_sync(0xffffffffu, sm, off);
        s_alpha[w][lane] = ex / sm;
    }
    __syncthreads();

    // gather: lane covers channels 8*lane..8*lane+7 ; warp w does m = 4i+w
    const int hh = lane >> 3;
    float acc[8];
#pragma unroll
    for (int j = 0; j < 8; j++) acc[j] = 0.0f;

#pragma unroll
    for (int i = 0; i < 8; i++) {
        int m = i * 4 + w;
        int row = s_nbr[m];
        float al = s_alpha[hh][m];
        uint4 v = *reinterpret_cast<const uint4*>(&g_hproj_h2[row * (OUTDIM / 2) + lane * 4]);
        float2 f0 = __half22float2(*reinterpret_cast<__half2*>(&v.x));
        float2 f1 = __half22float2(*reinterpret_cast<__half2*>(&v.y));
        float2 f2 = __half22float2(*reinterpret_cast<__half2*>(&v.z));
        float2 f3 = __half22float2(*reinterpret_cast<__half2*>(&v.w));
        acc[0] = fmaf(al, f0.x, acc[0]); acc[1] = fmaf(al, f0.y, acc[1]);
        acc[2] = fmaf(al, f1.x, acc[2]); acc[3] = fmaf(al, f1.y, acc[3]);
        acc[4] = fmaf(al, f2.x, acc[4]); acc[5] = fmaf(al, f2.y, acc[5]);
        acc[6] = fmaf(al, f3.x, acc[6]); acc[7] = fmaf(al, f3.y, acc[7]);
    }
    *reinterpret_cast<float4*>(&s_part[w][lane * 8])     = make_float4(acc[0], acc[1], acc[2], acc[3]);
    *reinterpret_cast<float4*>(&s_part[w][lane * 8 + 4]) = make_float4(acc[4], acc[5], acc[6], acc[7]);
    __syncthreads();

    // final: thread owns channels 2*tid, 2*tid+1
    const int c = 2 * tid;
    float2 p0 = *reinterpret_cast<const float2*>(&s_part[0][c]);
    float2 p1 = *reinterpret_cast<const float2*>(&s_part[1][c]);
    float2 p2 = *reinterpret_cast<const float2*>(&s_part[2][c]);
    float2 p3 = *reinterpret_cast<const float2*>(&s_part[3][c]);
    float ax = p0.x + p1.x + p2.x + p3.x;
    float ay = p0.y + p1.y + p2.y + p3.y;

    uint32_t rv = g_hproj_h2[n * (OUTDIM / 2) + tid];
    float2 res = __half22float2(*reinterpret_cast<__half2*>(&rv));
    float x0 = ax + res.x;
    float x1 = ay + res.y;
    float g0 = 0.5f * x0 * (1.0f + erff(x0 * 0.70710678118654752f));
    float g1 = 0.5f * x1 * (1.0f + erff(x1 * 0.70710678118654752f));

    float s1 = g0 + g1;
    float s2 = g0 * g0 + g1 * g1;
#pragma unroll
    for (int off = 16; off > 0; off >>= 1) {
        s1 += __shfl_xor_sync(0xffffffffu, s1, off);
        s2 += __shfl_xor_sync(0xffffffffu, s2, off);
    }
    if (lane == 0) { s_red[0][w] = s1; s_red[1][w] = s2; }
    __syncthreads();
    float S1 = s_red[0][0] + s_red[0][1] + s_red[0][2] + s_red[0][3];
    float S2 = s_red[1][0] + s_red[1][1] + s_red[1][2] + s_red[1][3];
    float mean = S1 * (1.0f / 256.0f);
    float var = S2 * (1.0f / 256.0f) - mean * mean;
    float inv = rsqrtf(var + LN_EPS);

    float2 gm = *reinterpret_cast<const float2*>(&gamma[c]);
    float2 bt = *reinterpret_cast<const float2*>(&beta[c]);
    float o0 = (g0 - mean) * inv * gm.x + bt.x;
    float o1 = (g1 - mean) * inv * gm.y + bt.y;
    *reinterpret_cast<float2*>(&out[n * OUTDIM + c]) = make_float2(o0, o1);
}

// ----------------------------------------------------------------------------
extern "C" void kernel_launch(void* const* d_in, const int* in_sizes, int n_in,
                              void* d_out, int out_size) {
    const float* h     = (const float*)d_in[0];
    const int*   nidx  = (const int*)  d_in[1];
    const int*   nmask = (const int*)  d_in[2];
    const float* W     = (const float*)d_in[3];
    const float* a_l   = (const float*)d_in[4];
    const float* a_r   = (const float*)d_in[5];
    const float* gamma = (const float*)d_in[6];
    const float* beta  = (const float*)d_in[7];
    float* out = (float*)d_out;

    cudaFuncSetAttribute(gemm_f16_kernel,
                         cudaFuncAttributeMaxDynamicSharedMemorySize, GEMM_SMEM_BYTES);

    convert_kernel<<<2048, 256>>>(h, W);
    dim3 ggrid((NN + 127) / 128, 4);
    gemm_f16_kernel<<<ggrid, 256, GEMM_SMEM_BYTES>>>();
    eler_kernel<<<(NN + 7) / 8, 256>>>(a_l, a_r);
    attn_kernel<<<NN, 128>>>(nidx, nmask, gamma, beta, out);
}